// round 5
// baseline (speedup 1.0000x reference)
#include <cuda_runtime.h>
#include <math.h>

// ---------------------------------------------------------------------------
// Problem constants
// ---------------------------------------------------------------------------
constexpr int B_ = 16;
constexpr int H_ = 512;
constexpr int W_ = 512;
constexpr int NPIX = H_ * W_;          // 262144 = 2^18
constexpr int NB = B_ * NPIX;          // 4194304

// ---------------------------------------------------------------------------
// Scratch (static __device__ arrays: the sanctioned no-alloc workaround)
// ---------------------------------------------------------------------------
__device__ float g_gray[NB];
__device__ float g_t0[NB];
__device__ float g_t1[NB];
__device__ float g_mag[NB];
__device__ unsigned char g_q[NB];
__device__ unsigned char g_edge[NB];
__device__ unsigned char g_weak[NB];
__device__ float g_comb[NB];
__device__ float g_h1[16 * NB];
__device__ float g_h2[16 * NB];
__device__ float g_h3[8 * NB];
__device__ float g_deep[NB];
__device__ float g_ce[2 * NB];
__device__ float g_r1[8 * NB];
__device__ float g_r2[4 * NB];
__device__ float g_refined[NB];
__device__ int g_flags[2];
__device__ int g_barcnt;
__device__ int g_barphase;

struct K5 { float k[5]; };

// ---------------------------------------------------------------------------
// Canny-path arithmetic canonicalized to XLA:CPU's naive emitter: separate
// IEEE fmul/fadd (NO fma anywhere in the binary-decision path), taps in
// row-major order, accumulator starting at 0, zero taps skipped (exact).
// ---------------------------------------------------------------------------
__global__ void __launch_bounds__(256) gray_kernel(const float* __restrict__ x,
                                                   float* __restrict__ gray) {
    int idx = blockIdx.x * 256 + threadIdx.x;
    if (idx >= NB) return;
    int b = idx >> 18;
    int p = idx & (NPIX - 1);
    const float* xb = x + (size_t)b * 3 * NPIX;
    float t0 = __fmul_rn(0.299f, xb[p]);
    float t1 = __fmul_rn(0.587f, xb[NPIX + p]);
    float t2 = __fmul_rn(0.114f, xb[2 * NPIX + p]);
    gray[idx] = __fadd_rn(__fadd_rn(t0, t1), t2);
}

__global__ void __launch_bounds__(256) blur_v_kernel(const float* __restrict__ in,
                                                     float* __restrict__ out, K5 kk) {
    int idx = blockIdx.x * 256 + threadIdx.x;
    if (idx >= NB) return;
    int p = idx & (NPIX - 1);
    int y = p >> 9;
    int x = p & 511;
    const float* ib = in + (idx - p);
    float s = 0.f;
#pragma unroll
    for (int i = 0; i < 5; i++) {
        int yy = y + i - 2;
        if ((unsigned)yy < (unsigned)H_)
            s = __fadd_rn(s, __fmul_rn(kk.k[i], ib[yy * W_ + x]));
    }
    out[idx] = s;
}

__global__ void __launch_bounds__(256) blur_h_kernel(const float* __restrict__ in,
                                                     float* __restrict__ out, K5 kk) {
    int idx = blockIdx.x * 256 + threadIdx.x;
    if (idx >= NB) return;
    int p = idx & (NPIX - 1);
    int x = p & 511;
    const float* ib = in + (idx - x);   // row base
    float s = 0.f;
#pragma unroll
    for (int i = 0; i < 5; i++) {
        int xx = x + i - 2;
        if ((unsigned)xx < (unsigned)W_)
            s = __fadd_rn(s, __fmul_rn(kk.k[i], ib[xx]));
    }
    out[idx] = s;
}

// Sobel magnitude + quantized direction bin (q = round(ang * (4/pi)) mod 4)
__global__ void __launch_bounds__(256) magq_kernel(const float* __restrict__ in,
                                                   float* __restrict__ mag,
                                                   unsigned char* __restrict__ q) {
    int idx = blockIdx.x * 256 + threadIdx.x;
    if (idx >= NB) return;
    int p = idx & (NPIX - 1);
    int y = p >> 9;
    int x = p & 511;
    const float* ib = in + (idx - p);
    float a[3][3];
#pragma unroll
    for (int dy = 0; dy < 3; dy++)
#pragma unroll
        for (int dx = 0; dx < 3; dx++) {
            int yy = y + dy - 1, xx = x + dx - 1;
            float v = 0.f;
            if ((unsigned)yy < (unsigned)H_ && (unsigned)xx < (unsigned)W_)
                v = ib[yy * W_ + xx];
            a[dy][dx] = v;
        }
    // sx = [[-1,0,1],[-2,0,2],[-1,0,1]]  mul+add chain, row-major taps
    float gx = 0.f;
    gx = __fadd_rn(gx, __fmul_rn(-1.f, a[0][0]));
    gx = __fadd_rn(gx, __fmul_rn( 1.f, a[0][2]));
    gx = __fadd_rn(gx, __fmul_rn(-2.f, a[1][0]));
    gx = __fadd_rn(gx, __fmul_rn( 2.f, a[1][2]));
    gx = __fadd_rn(gx, __fmul_rn(-1.f, a[2][0]));
    gx = __fadd_rn(gx, __fmul_rn( 1.f, a[2][2]));
    // sy = [[-1,-2,-1],[0,0,0],[1,2,1]]
    float gy = 0.f;
    gy = __fadd_rn(gy, __fmul_rn(-1.f, a[0][0]));
    gy = __fadd_rn(gy, __fmul_rn(-2.f, a[0][1]));
    gy = __fadd_rn(gy, __fmul_rn(-1.f, a[0][2]));
    gy = __fadd_rn(gy, __fmul_rn( 1.f, a[2][0]));
    gy = __fadd_rn(gy, __fmul_rn( 2.f, a[2][1]));
    gy = __fadd_rn(gy, __fmul_rn( 1.f, a[2][2]));
    float m = sqrtf(__fadd_rn(__fadd_rn(__fmul_rn(gx, gx), __fmul_rn(gy, gy)), 1e-12f));
    // Correctly-rounded float atan2: double atan2 rounded once to float.
    float ang = (float)atan2((double)gy, (double)gx);
    const float pi4 = 0.78539816339744830962f;       // f32(pi/4)
    int qi = (int)rintf(__fdiv_rn(ang, pi4));        // round-half-even
    qi = ((qi % 4) + 4) % 4;
    mag[idx] = m;
    q[idx] = (unsigned char)qi;
}

__global__ void __launch_bounds__(256) nms_kernel(const float* __restrict__ mag,
                                                  const unsigned char* __restrict__ q,
                                                  unsigned char* __restrict__ edge,
                                                  unsigned char* __restrict__ weak) {
    int idx = blockIdx.x * 256 + threadIdx.x;
    if (idx >= NB) return;
    int p = idx & (NPIX - 1);
    int y = p >> 9;
    int x = p & 511;
    const float* mb = mag + (idx - p);
    float m = mag[idx];
    int qq = q[idx];
    int day, dax, dby, dbx;
    if (qq == 0)      { day = 0;  dax = 1;  dby = 0;  dbx = -1; }
    else if (qq == 1) { day = -1; dax = 1;  dby = 1;  dbx = -1; }
    else if (qq == 2) { day = -1; dax = 0;  dby = 1;  dbx = 0;  }
    else              { day = -1; dax = -1; dby = 1;  dbx = 1;  }
    float na = 0.f, nb = 0.f;
    {
        int yy = y + day, xx = x + dax;
        if ((unsigned)yy < (unsigned)H_ && (unsigned)xx < (unsigned)W_) na = mb[yy * W_ + xx];
        yy = y + dby; xx = x + dbx;
        if ((unsigned)yy < (unsigned)H_ && (unsigned)xx < (unsigned)W_) nb = mb[yy * W_ + xx];
    }
    float nmsv = (m >= na && m >= nb) ? m : 0.f;
    edge[idx] = (nmsv > 0.2f) ? 1 : 0;
    weak[idx] = (nmsv > 0.1f && nmsv <= 0.2f) ? 1 : 0;
}

__global__ void __launch_bounds__(256) combine_kernel(const unsigned char* __restrict__ e,
                                                      float* __restrict__ comb, int first) {
    int idx = blockIdx.x * 256 + threadIdx.x;
    if (idx >= NB) return;
    float v = (float)e[idx];
    comb[idx] = first ? v : fmaxf(comb[idx], v);
}

__global__ void clear_sync_kernel() {
    if (threadIdx.x == 0) {
        g_flags[0] = 0;
        g_flags[1] = 0;
        g_barcnt = 0;
        g_barphase = 0;
    }
}

// ---------------------------------------------------------------------------
// Persistent hysteresis kernel (unique monotone fixpoint -> deterministic)
// ---------------------------------------------------------------------------
__device__ __forceinline__ void grid_barrier(int* phase) {
    __syncthreads();
    if (threadIdx.x == 0 && threadIdx.y == 0) {
        __threadfence();
        int target = *phase + 1;
        if (atomicAdd(&g_barcnt, 1) == (int)gridDim.x - 1) {
            g_barcnt = 0;
            __threadfence();
            atomicExch(&g_barphase, target);
        } else {
            while (atomicAdd(&g_barphase, 0) < target) { __nanosleep(64); }
        }
        __threadfence();
        *phase = target;
    }
    __syncthreads();
}

__global__ void __launch_bounds__(256) hysteresis_kernel(int ntiles) {
    __shared__ unsigned char se[34][34];
    __shared__ unsigned char sw[32][32];
    const int tid = threadIdx.y * 32 + threadIdx.x;
    int phase = 0;
    for (int it = 0;; it++) {
        if (blockIdx.x == 0 && tid == 0) {
            ((volatile int*)g_flags)[(it + 1) & 1] = 0;
        }
        int any = 0;
        for (int t = blockIdx.x; t < ntiles; t += gridDim.x) {
            __syncthreads();  // protect smem reuse across tiles
            int b = t >> 8;                 // 256 tiles per image (16x16)
            int ti = t & 255;
            int ty0 = (ti >> 4) << 5;
            int tx0 = (ti & 15) << 5;
            const size_t base = (size_t)b << 18;
            for (int i = tid; i < 34 * 34; i += 256) {
                int r = i / 34, c = i % 34;
                int y = ty0 + r - 1, x = tx0 + c - 1;
                unsigned char v = 0;
                if ((unsigned)y < (unsigned)H_ && (unsigned)x < (unsigned)W_)
                    v = g_edge[base + ((size_t)y << 9) + x];
                se[r][c] = v;
            }
            bool myneed = false;
#pragma unroll
            for (int k2 = 0; k2 < 4; k2++) {
                int r = threadIdx.y + 8 * k2;
                int y = ty0 + r, x = tx0 + threadIdx.x;
                unsigned char wv = g_weak[base + ((size_t)y << 9) + x];
                sw[r][threadIdx.x] = wv;
                if (wv) myneed = true;
            }
            if (!__syncthreads_or(myneed ? 1 : 0)) continue;
            bool tilechanged = false;
            for (;;) {
                bool ch = false;
#pragma unroll
                for (int k2 = 0; k2 < 4; k2++) {
                    int r = threadIdx.y + 8 * k2;
                    int c = threadIdx.x;
                    if (sw[r][c] && !se[r + 1][c + 1]) {
                        int n = se[r][c] | se[r][c + 1] | se[r][c + 2]
                              | se[r + 1][c] | se[r + 1][c + 2]
                              | se[r + 2][c] | se[r + 2][c + 1] | se[r + 2][c + 2];
                        if (n) { se[r + 1][c + 1] = 1; ch = true; }
                    }
                }
                if (__syncthreads_or(ch ? 1 : 0)) tilechanged = true;
                else break;
            }
            if (tilechanged) {
                any = 1;
#pragma unroll
                for (int k2 = 0; k2 < 4; k2++) {
                    int r = threadIdx.y + 8 * k2;
                    int y = ty0 + r, x = tx0 + threadIdx.x;
                    g_edge[base + ((size_t)y << 9) + x] = se[r + 1][threadIdx.x + 1];
                }
            }
        }
        if (any && tid == 0) ((volatile int*)g_flags)[it & 1] = 1;
        grid_barrier(&phase);
        int f = ((volatile int*)g_flags)[it & 1];
        grid_barrier(&phase);
        if (!f) break;
    }
}

// ---------------------------------------------------------------------------
// Direct 3x3 SAME conv (zero pad), all out-channels per thread, fused act
// ACT: 0 = leaky relu (0.2), 1 = sigmoid
// ---------------------------------------------------------------------------
template <int CIN, int COUT, int ACT>
__global__ void __launch_bounds__(256) conv3x3_k(const float* __restrict__ in,
                                                 const float* __restrict__ wt,
                                                 const float* __restrict__ bias,
                                                 float* __restrict__ out) {
    __shared__ float s_in[CIN][10][34];
    __shared__ float s_w[COUT * CIN * 9];
    __shared__ float s_b[COUT];
    const int tid = threadIdx.y * 32 + threadIdx.x;
    const int b = blockIdx.z;
    const int x0 = blockIdx.x * 32, y0 = blockIdx.y * 8;
    for (int i = tid; i < COUT * CIN * 9; i += 256) s_w[i] = wt[i];
    if (tid < COUT) s_b[tid] = bias[tid];
    const float* inb = in + (size_t)b * CIN * NPIX;
    for (int i = tid; i < CIN * 340; i += 256) {
        int c = i / 340;
        int rr = (i / 34) % 10;
        int cc = i % 34;
        int y = y0 + rr - 1, x = x0 + cc - 1;
        float v = 0.f;
        if ((unsigned)y < (unsigned)H_ && (unsigned)x < (unsigned)W_)
            v = inb[(size_t)c * NPIX + y * W_ + x];
        s_in[c][rr][cc] = v;
    }
    __syncthreads();
    float acc[COUT];
#pragma unroll
    for (int co = 0; co < COUT; co++) acc[co] = s_b[co];
    const int ly = threadIdx.y, lx = threadIdx.x;
#pragma unroll
    for (int ci = 0; ci < CIN; ci++) {
        float v[9];
#pragma unroll
        for (int r = 0; r < 3; r++)
#pragma unroll
            for (int c = 0; c < 3; c++) v[r * 3 + c] = s_in[ci][ly + r][lx + c];
#pragma unroll
        for (int co = 0; co < COUT; co++) {
#pragma unroll
            for (int k = 0; k < 9; k++)
                acc[co] += s_w[(co * CIN + ci) * 9 + k] * v[k];
        }
    }
    float* ob = out + (size_t)b * COUT * NPIX + (y0 + ly) * W_ + (x0 + lx);
#pragma unroll
    for (int co = 0; co < COUT; co++) {
        float r = acc[co];
        if (ACT == 0) r = (r >= 0.f) ? r : 0.2f * r;
        else r = 1.f / (1.f + expf(-r));
        ob[(size_t)co * NPIX] = r;
    }
}

__global__ void __launch_bounds__(256) pack_ce_kernel(const float* __restrict__ comb,
                                                      const float* __restrict__ deep,
                                                      float* __restrict__ ce) {
    int idx = blockIdx.x * 256 + threadIdx.x;
    if (idx >= NB) return;
    int b = idx >> 18;
    int p = idx & (NPIX - 1);
    float* cb = ce + (size_t)b * 2 * NPIX;
    cb[p] = comb[idx];
    cb[NPIX + p] = deep[idx];
}

__global__ void __launch_bounds__(256) final_kernel(const float* __restrict__ refined,
                                                    const float* __restrict__ deep,
                                                    const float* __restrict__ comb,
                                                    const float* __restrict__ mask,
                                                    float* __restrict__ out) {
    int idx = blockIdx.x * 256 + threadIdx.x;
    if (idx >= NB) return;
    int b = idx >> 18;
    int p = idx & (NPIX - 1);
    float r = refined[idx];
    float d = deep[idx];
    float m = mask[idx];
    float c = comb[idx];
    float em = __fadd_rn(__fmul_rn(r, __fadd_rn(1.f, -m)),
                         __fmul_rn(__fmul_rn(d, m), 0.5f));
    const size_t T = (size_t)NB;
    out[idx] = em;                                   // edge_map
    float* ef = out + T + (size_t)b * 2 * NPIX;      // edge_features
    ef[p] = em;
    ef[NPIX + p] = d;
    out[3 * T + idx] = c;                            // combined_canny
    out[4 * T + idx] = d;                            // deep_edges
}

// ---------------------------------------------------------------------------
// Host side
// ---------------------------------------------------------------------------
static void gauss5(float sigma, float* k) {
    float kk[5];
    for (int i = 0; i < 5; i++) {
        float r = (float)i - 2.0f;
        float rr = r * r;
        float denom = (float)(2.0 * (double)sigma * (double)sigma);
        float arg = -(rr / denom);
        kk[i] = (float)exp((double)arg);
    }
    float sum = ((((kk[0] + kk[1]) + kk[2]) + kk[3]) + kk[4]);
    for (int i = 0; i < 5; i++) k[i] = kk[i] / sum;
}

extern "C" void kernel_launch(void* const* d_in, const int* in_sizes, int n_in,
                              void* d_out, int out_size) {
    const float* x    = (const float*)d_in[0];
    const float* mask = (const float*)d_in[1];
    const float* wd1 = (const float*)d_in[2];
    const float* bd1 = (const float*)d_in[3];
    const float* wd2 = (const float*)d_in[4];
    const float* bd2 = (const float*)d_in[5];
    const float* wd3 = (const float*)d_in[6];
    const float* bd3 = (const float*)d_in[7];
    const float* wd4 = (const float*)d_in[8];
    const float* bd4 = (const float*)d_in[9];
    const float* wr1 = (const float*)d_in[10];
    const float* br1 = (const float*)d_in[11];
    const float* wr2 = (const float*)d_in[12];
    const float* br2 = (const float*)d_in[13];
    const float* wr3 = (const float*)d_in[14];
    const float* br3 = (const float*)d_in[15];
    float* out = (float*)d_out;

    float *p_gray, *p_t0, *p_t1, *p_mag, *p_comb, *p_h1, *p_h2, *p_h3;
    float *p_deep, *p_ce, *p_r1, *p_r2, *p_refined;
    unsigned char *p_q, *p_e, *p_w;
    cudaGetSymbolAddress((void**)&p_gray, g_gray);
    cudaGetSymbolAddress((void**)&p_t0, g_t0);
    cudaGetSymbolAddress((void**)&p_t1, g_t1);
    cudaGetSymbolAddress((void**)&p_mag, g_mag);
    cudaGetSymbolAddress((void**)&p_comb, g_comb);
    cudaGetSymbolAddress((void**)&p_h1, g_h1);
    cudaGetSymbolAddress((void**)&p_h2, g_h2);
    cudaGetSymbolAddress((void**)&p_h3, g_h3);
    cudaGetSymbolAddress((void**)&p_deep, g_deep);
    cudaGetSymbolAddress((void**)&p_ce, g_ce);
    cudaGetSymbolAddress((void**)&p_r1, g_r1);
    cudaGetSymbolAddress((void**)&p_r2, g_r2);
    cudaGetSymbolAddress((void**)&p_refined, g_refined);
    cudaGetSymbolAddress((void**)&p_q, g_q);
    cudaGetSymbolAddress((void**)&p_e, g_edge);
    cudaGetSymbolAddress((void**)&p_w, g_weak);

    const int egrid = NB / 256;
    gray_kernel<<<egrid, 256>>>(x, p_gray);

    float ks[3][5];
    gauss5(0.5f, ks[0]);
    gauss5(1.0f, ks[1]);
    gauss5(2.0f, ks[2]);
    K5 kint;
    gauss5(1.0f, kint.k);

    int dev = 0;
    cudaGetDevice(&dev);
    int sms = 0;
    cudaDeviceGetAttribute(&sms, cudaDevAttrMultiProcessorCount, dev);
    int per = 0;
    cudaOccupancyMaxActiveBlocksPerMultiprocessor(&per, hysteresis_kernel, 256, 0);
    if (per < 1) per = 1;
    int hgrid = sms * per;
    const int ntiles = B_ * 256;
    if (hgrid > ntiles) hgrid = ntiles;
    if (hgrid < 1) hgrid = 1;

    for (int s = 0; s < 3; s++) {
        K5 kv;
        for (int i = 0; i < 5; i++) kv.k[i] = ks[s][i];
        blur_v_kernel<<<egrid, 256>>>(p_gray, p_t0, kv);
        blur_h_kernel<<<egrid, 256>>>(p_t0, p_t1, kv);
        blur_v_kernel<<<egrid, 256>>>(p_t1, p_t0, kint);   // canny internal blur sigma=1
        blur_h_kernel<<<egrid, 256>>>(p_t0, p_t1, kint);
        magq_kernel<<<egrid, 256>>>(p_t1, p_mag, p_q);
        nms_kernel<<<egrid, 256>>>(p_mag, p_q, p_e, p_w);
        clear_sync_kernel<<<1, 32>>>();
        hysteresis_kernel<<<hgrid, dim3(32, 8)>>>(ntiles);
        combine_kernel<<<egrid, 256>>>(p_e, p_comb, s == 0 ? 1 : 0);
    }

    dim3 cb(32, 8);
    dim3 cg(W_ / 32, H_ / 8, B_);
    conv3x3_k<3, 16, 0><<<cg, cb>>>(x, wd1, bd1, p_h1);
    conv3x3_k<16, 16, 0><<<cg, cb>>>(p_h1, wd2, bd2, p_h2);
    conv3x3_k<16, 8, 0><<<cg, cb>>>(p_h2, wd3, bd3, p_h3);
    conv3x3_k<8, 1, 1><<<cg, cb>>>(p_h3, wd4, bd4, p_deep);

    pack_ce_kernel<<<egrid, 256>>>(p_comb, p_deep, p_ce);
    conv3x3_k<2, 8, 0><<<cg, cb>>>(p_ce, wr1, br1, p_r1);
    conv3x3_k<8, 4, 0><<<cg, cb>>>(p_r1, wr2, br2, p_r2);
    conv3x3_k<4, 1, 1><<<cg, cb>>>(p_r2, wr3, br3, p_refined);

    final_kernel<<<egrid, 256>>>(p_refined, p_deep, p_comb, mask, out);
}